// round 16
// baseline (speedup 1.0000x reference)
#include <cuda_runtime.h>
#include <cstdint>

#define Bb 32
#define Cc 32
#define Tt 2048
#define Dd 512
#define ALPHA 0.1f
#define BETA  0.9f

#define SEG   256
#define NSEG  (Tt / SEG)          // 8
#define NSCAN_BLK ((Bb * Cc * NSEG) / 8)   // 1024
#define PE 16

#define NTILES   2048             // 16 tB x 4 eB x 32 b
#define NPERSIST 296              // 148 SMs x 2 CTA

// Scratch (no cudaMalloc allowed)
__device__ float g_s[Bb*Cc*Tt];       // 0.5 * (fwd + bwd EWMA of diff)  [b][c][t]
__device__ float g_wc[Cc*Dd];         // Wcomb c-major: g_wc[c*Dd + e]
__device__ float g_bcomb[Dd];         // W_lin @ b_ve + b_lin

#define FMA_F32X2(d, a, b, c) \
    asm("fma.rn.f32x2 %0, %1, %2, %3;" : "=l"(d) : "l"(a), "l"(b), "l"(c))
#define PACK_DUP(d, f) \
    asm("mov.b64 %0, {%1, %1};" : "=l"(d) : "f"(f))

static __device__ __forceinline__ float2 unpack_f32x2(unsigned long long v) {
    float2 r;
    asm("mov.b64 {%0, %1}, %2;" : "=f"(r.x), "=f"(r.y) : "l"(v));
    return r;
}
static __device__ __forceinline__ void cp_async16(uint32_t saddr, const void* g) {
    asm volatile("cp.async.cg.shared.global [%0], [%1], 16;"
                 :: "r"(saddr), "l"(g) : "memory");
}
#define CP_COMMIT() asm volatile("cp.async.commit_group;" ::: "memory")
#define CP_WAIT1()  asm volatile("cp.async.wait_group 1;" ::: "memory")

// ---------------------------------------------------------------------------
// P: smem-tiled mini-GEMM for Wcomb = W_lin @ W_ve (c-major out) + bias.
// ---------------------------------------------------------------------------
__global__ void __launch_bounds__(256) prep_kernel(
    const float* __restrict__ W_ve, const float* __restrict__ b_ve,
    const float* __restrict__ W_lin, const float* __restrict__ b_lin)
{
    __shared__ float wlin_sm[128 * 17];
    __shared__ float wve_sm[128 * 36];

    int tid = threadIdx.x;
    int e0 = blockIdx.x * PE;
    int tx = tid & 15;
    int ty = tid >> 4;

    float2 acc = make_float2(0.f, 0.f);

    for (int ch = 0; ch < 4; ch++) {
        int dBase = ch * 128;
        __syncthreads();

        #pragma unroll
        for (int k = 0; k < 2; k++) {
            int idx = tid + k * 256;
            int e   = idx >> 5;
            int d4  = (idx & 31) * 4;
            float4 w = *(const float4*)(W_lin + (size_t)(e0 + e) * Dd + dBase + d4);
            wlin_sm[(d4 + 0) * 17 + e] = w.x;
            wlin_sm[(d4 + 1) * 17 + e] = w.y;
            wlin_sm[(d4 + 2) * 17 + e] = w.z;
            wlin_sm[(d4 + 3) * 17 + e] = w.w;
        }
        #pragma unroll
        for (int k = 0; k < 4; k++) {
            int idx = tid + k * 256;
            int d   = idx >> 3;
            int c4  = (idx & 7) * 4;
            float4 v = *(const float4*)(W_ve + (size_t)(dBase + d) * Cc + c4);
            *(float4*)&wve_sm[d * 36 + c4] = v;
        }
        __syncthreads();

        #pragma unroll 8
        for (int dl = 0; dl < 128; dl++) {
            float  wl  = wlin_sm[dl * 17 + ty];
            float2 wv2 = *(const float2*)&wve_sm[dl * 36 + tx * 2];
            acc.x = fmaf(wl, wv2.x, acc.x);
            acc.y = fmaf(wl, wv2.y, acc.y);
        }
    }

    int e = e0 + ty;
    g_wc[(2 * tx)     * Dd + e] = acc.x;
    g_wc[(2 * tx + 1) * Dd + e] = acc.y;

    const unsigned FULL = 0xffffffffu;
    int wid  = tid >> 5;
    int lane = tid & 31;
    #pragma unroll
    for (int r = 0; r < 2; r++) {
        int eb = e0 + 2 * wid + r;
        float a = 0.f;
        #pragma unroll
        for (int i = 0; i < 16; i++) {
            int d = lane + 32 * i;
            a = fmaf(W_lin[(size_t)eb * Dd + d], b_ve[d], a);
        }
        a += __shfl_down_sync(FULL, a, 16);
        a += __shfl_down_sync(FULL, a, 8);
        a += __shfl_down_sync(FULL, a, 4);
        a += __shfl_down_sync(FULL, a, 2);
        a += __shfl_down_sync(FULL, a, 1);
        if (lane == 0) g_bcomb[eb] = a + b_lin[eb];
    }
}

// ---------------------------------------------------------------------------
// S: fused bidirectional EWMA of first-difference (R14 body, measured 9.7us).
// ---------------------------------------------------------------------------
__global__ void __launch_bounds__(256) scan_kernel(const float* __restrict__ x)
{
    const unsigned FULL = 0xffffffffu;
    int g    = blockIdx.x * 8 + (threadIdx.x >> 5);
    int lane = threadIdx.x & 31;
    int bc   = g >> 3;
    int seg  = g & 7;

    const float* row = x + (size_t)bc * Tt;
    float*      srow = g_s + (size_t)bc * Tt;
    int lo = seg * SEG;
    int hi = lo + SEG;

    const float q   = 0.43046721f;              // 0.9^8
    const float q2  = q * q;
    const float q4  = q2 * q2;
    const float q8  = q4 * q4;
    const float q16 = q8 * q8;
    float blE;
    {
        float p = 1.f, base = q;
        int n = lane;
        while (n) { if (n & 1) p *= base; base *= base; n >>= 1; }
        blE = p;
    }
    const float B256 = 1.9e-12f;

    float Ff[8];

    {   // forward pass
        float warpCarry = 0.f;
        int t0 = (seg == 0) ? lo : (lo - SEG);
        for (; t0 < hi; t0 += SEG) {
            int tb = t0 + lane * 8;
            float4 a  = *(const float4*)(row + tb);
            float4 bq = *(const float4*)(row + tb + 4);
            float e[8] = {a.x, a.y, a.z, a.w, bq.x, bq.y, bq.z, bq.w};
            float prev = __shfl_up_sync(FULL, bq.w, 1);
            if (lane == 0) prev = (tb > 0) ? row[tb - 1] : 0.f;

            float L[8];
            L[0] = (tb == 0) ? 0.f : ALPHA * (e[0] - prev);
            #pragma unroll
            for (int j = 1; j < 8; j++)
                L[j] = fmaf(BETA, L[j - 1], ALPHA * (e[j] - e[j - 1]));

            float v = L[7], vo;
            vo = __shfl_up_sync(FULL, v, 1);  if (lane >= 1)  v = fmaf(q,   vo, v);
            vo = __shfl_up_sync(FULL, v, 2);  if (lane >= 2)  v = fmaf(q2,  vo, v);
            vo = __shfl_up_sync(FULL, v, 4);  if (lane >= 4)  v = fmaf(q4,  vo, v);
            vo = __shfl_up_sync(FULL, v, 8);  if (lane >= 8)  v = fmaf(q8,  vo, v);
            vo = __shfl_up_sync(FULL, v, 16); if (lane >= 16) v = fmaf(q16, vo, v);
            float vprev = __shfl_up_sync(FULL, v, 1);
            if (lane == 0) vprev = 0.f;
            float C = fmaf(blE, warpCarry, vprev);

            float coef = BETA;
            if (t0 >= lo) {
                #pragma unroll
                for (int j = 0; j < 8; j++) { Ff[j] = fmaf(coef, C, L[j]); coef *= BETA; }
            }
            float v31 = __shfl_sync(FULL, v, 31);
            warpCarry = fmaf(B256, warpCarry, v31);
        }
    }

    {   // backward pass + combine
        bool last = (hi == Tt);
        float warpCarry = last ? (row[Tt - 1] - row[Tt - 2]) : 0.f;
        int tt = last ? (Tt - 1) : (hi + SEG - 1);
        for (; tt >= lo; tt -= SEG) {
            int tb = tt - lane * 8;
            float4 a  = *(const float4*)(row + tb - 7);
            float4 bq = *(const float4*)(row + tb - 3);
            float e[8] = {bq.w, bq.z, bq.y, bq.x, a.w, a.z, a.y, a.x};
            float prev = __shfl_down_sync(FULL, bq.w, 1);
            if (lane == 31) prev = (tb - 8 >= 0) ? row[tb - 8] : 0.f;

            float L[8];
            L[0] = ALPHA * (e[0] - e[1]);
            #pragma unroll
            for (int j = 1; j < 7; j++)
                L[j] = fmaf(BETA, L[j - 1], ALPHA * (e[j] - e[j + 1]));
            {
                float d7 = (tb - 7 == 0) ? 0.f : (e[7] - prev);
                L[7] = fmaf(BETA, L[6], ALPHA * d7);
            }

            float v = L[7], vo;
            vo = __shfl_up_sync(FULL, v, 1);  if (lane >= 1)  v = fmaf(q,   vo, v);
            vo = __shfl_up_sync(FULL, v, 2);  if (lane >= 2)  v = fmaf(q2,  vo, v);
            vo = __shfl_up_sync(FULL, v, 4);  if (lane >= 4)  v = fmaf(q4,  vo, v);
            vo = __shfl_up_sync(FULL, v, 8);  if (lane >= 8)  v = fmaf(q8,  vo, v);
            vo = __shfl_up_sync(FULL, v, 16); if (lane >= 16) v = fmaf(q16, vo, v);
            float vprev = __shfl_up_sync(FULL, v, 1);
            if (lane == 0) vprev = 0.f;
            float C = fmaf(blE, warpCarry, vprev);

            if (tt < hi) {
                float Fb[8];
                float coef = BETA;
                #pragma unroll
                for (int j = 0; j < 8; j++) { Fb[j] = fmaf(coef, C, L[j]); coef *= BETA; }
                float recv[8];
                #pragma unroll
                for (int j = 0; j < 8; j++)
                    recv[j] = __shfl_xor_sync(FULL, Fb[j], 31);
                int tbf = lo + lane * 8;
                float4 o0 = make_float4(0.5f * (Ff[0] + recv[7]),
                                        0.5f * (Ff[1] + recv[6]),
                                        0.5f * (Ff[2] + recv[5]),
                                        0.5f * (Ff[3] + recv[4]));
                float4 o1 = make_float4(0.5f * (Ff[4] + recv[3]),
                                        0.5f * (Ff[5] + recv[2]),
                                        0.5f * (Ff[6] + recv[1]),
                                        0.5f * (Ff[7] + recv[0]));
                *(float4*)(srow + tbf)     = o0;
                *(float4*)(srow + tbf + 4) = o1;
            }
            float v31 = __shfl_sync(FULL, v, 31);
            warpCarry = fmaf(B256, warpCarry, v31);
        }
    }
}

// ---------------------------------------------------------------------------
// G: persistent FFMA2 GEMM with cp.async double-buffered tile pipeline.
// 296 CTAs; each loops over tiles (idx = blockIdx.x + it*296).
// Per tile: mainloop identical to R10/R15 (measured 43.8us config); the
// s/w stage of tile i+1 overlaps the compute of tile i.
// Dynamic smem: 2 buffers x (ssm 16KB + wsm 16KB) = 64 KB.
// ---------------------------------------------------------------------------
__global__ void __launch_bounds__(256, 2) gemm_kernel(float* __restrict__ out)
{
    extern __shared__ float smem[];    // [2][8192]: per buf: s[32][128], w[32][128]
    uint32_t sbase = (uint32_t)__cvta_generic_to_shared(smem);

    int tid = threadIdx.x;
    int tx = tid & 15;
    int ty = tid >> 4;

    // Prologue: prefetch first tile into buffer 0.
    {
        int t0 = blockIdx.x;               // < NPERSIST <= NTILES
        int tB = t0 & 15, eB = (t0 >> 4) & 3, b = t0 >> 6;
        int tBase = tB * 128, eBase = eB * 128;
        #pragma unroll
        for (int k = 0; k < 4; k++) {
            int idx = tid + k * 256;
            int c   = idx >> 5;
            int q4i = (idx & 31) * 4;
            cp_async16(sbase + (uint32_t)(c * 128 + q4i) * 4,
                       g_s + ((size_t)(b * Cc + c)) * Tt + tBase + q4i);
            cp_async16(sbase + (uint32_t)(4096 + c * 128 + q4i) * 4,
                       g_wc + (size_t)c * Dd + eBase + q4i);
        }
        CP_COMMIT();
    }

    int buf = 0;
    for (int t = blockIdx.x; t < NTILES; t += NPERSIST) {
        // Prefetch next tile into the other buffer (empty commit if none).
        int tn = t + NPERSIST;
        if (tn < NTILES) {
            int tB = tn & 15, eB = (tn >> 4) & 3, b = tn >> 6;
            int tBase = tB * 128, eBase = eB * 128;
            uint32_t obase = sbase + (uint32_t)(buf ^ 1) * 32768u;
            #pragma unroll
            for (int k = 0; k < 4; k++) {
                int idx = tid + k * 256;
                int c   = idx >> 5;
                int q4i = (idx & 31) * 4;
                cp_async16(obase + (uint32_t)(c * 128 + q4i) * 4,
                           g_s + ((size_t)(b * Cc + c)) * Tt + tBase + q4i);
                cp_async16(obase + (uint32_t)(4096 + c * 128 + q4i) * 4,
                           g_wc + (size_t)c * Dd + eBase + q4i);
            }
        }
        CP_COMMIT();
        CP_WAIT1();                    // current tile's group complete
        __syncthreads();

        const float* S = smem + buf * 8192;          // [c][128]
        const float* W = smem + buf * 8192 + 4096;   // [c][128]

        unsigned long long acc[8][4];
        #pragma unroll
        for (int i = 0; i < 8; i++)
            #pragma unroll
            for (int p = 0; p < 4; p++) acc[i][p] = 0ull;

        #pragma unroll
        for (int c = 0; c < Cc; c++) {
            float4 s0 = *(const float4*)&S[c * 128 + ty * 8];
            float4 s1 = *(const float4*)&S[c * 128 + ty * 8 + 4];
            float sf[8] = {s0.x, s0.y, s0.z, s0.w, s1.x, s1.y, s1.z, s1.w};
            unsigned long long sv[8];
            #pragma unroll
            for (int i = 0; i < 8; i++) PACK_DUP(sv[i], sf[i]);

            ulonglong2 w0 = *(const ulonglong2*)&W[c * 128 + 4 * tx];
            ulonglong2 w1 = *(const ulonglong2*)&W[c * 128 + 4 * tx + 64];
            #pragma unroll
            for (int i = 0; i < 8; i++) {
                FMA_F32X2(acc[i][0], sv[i], w0.x, acc[i][0]);
                FMA_F32X2(acc[i][1], sv[i], w0.y, acc[i][1]);
                FMA_F32X2(acc[i][2], sv[i], w1.x, acc[i][2]);
                FMA_F32X2(acc[i][3], sv[i], w1.y, acc[i][3]);
            }
        }

        // Epilogue
        {
            int tB = t & 15, eB = (t >> 4) & 3, b = t >> 6;
            int tBase = tB * 128, eBase = eB * 128;
            float4 bias0 = *(const float4*)(g_bcomb + eBase + 4 * tx);
            float4 bias1 = *(const float4*)(g_bcomb + eBase + 4 * tx + 64);
            #pragma unroll
            for (int i = 0; i < 8; i++) {
                int tt = tBase + ty * 8 + i;
                float* base = out + ((size_t)(b * Tt + tt)) * Dd + eBase;
                float2 r0 = unpack_f32x2(acc[i][0]);
                float2 r1 = unpack_f32x2(acc[i][1]);
                float2 r2 = unpack_f32x2(acc[i][2]);
                float2 r3 = unpack_f32x2(acc[i][3]);
                float4 o0 = make_float4(r0.x + bias0.x, r0.y + bias0.y,
                                        r1.x + bias0.z, r1.y + bias0.w);
                float4 o1 = make_float4(r2.x + bias1.x, r2.y + bias1.y,
                                        r3.x + bias1.z, r3.y + bias1.w);
                *(float4*)(base + 4 * tx)      = o0;
                *(float4*)(base + 4 * tx + 64) = o1;
            }
        }

        __syncthreads();   // all reads of buf done before it is prefetched over
        buf ^= 1;
    }
}

// ---------------------------------------------------------------------------
extern "C" void kernel_launch(void* const* d_in, const int* in_sizes, int n_in,
                              void* d_out, int out_size)
{
    const float* x     = (const float*)d_in[0];   // [B, C, T]
    const float* W_ve  = (const float*)d_in[1];   // [D, C]
    const float* b_ve  = (const float*)d_in[2];   // [D]
    const float* W_lin = (const float*)d_in[3];   // [D, D]
    const float* b_lin = (const float*)d_in[4];   // [D]
    float* out = (float*)d_out;                   // [B, T, D]

    cudaFuncSetAttribute(gemm_kernel,
                         cudaFuncAttributeMaxDynamicSharedMemorySize, 65536);

    scan_kernel<<<NSCAN_BLK, 256>>>(x);
    prep_kernel<<<Dd / PE, 256>>>(W_ve, b_ve, W_lin, b_lin);

    gemm_kernel<<<NPERSIST, 256, 65536>>>(out);
}

// round 17
// speedup vs baseline: 1.0494x; 1.0494x over previous
#include <cuda_runtime.h>
#include <cstdint>

#define Bb 32
#define Cc 32
#define Tt 2048
#define Dd 512
#define ALPHA 0.1f
#define BETA  0.9f

#define SEG   512
#define NSEG  (Tt / SEG)          // 4
#define NSCAN_BLK ((Bb * Cc * NSEG) / 8)   // 512
#define PE 16

// Scratch (no cudaMalloc allowed)
__device__ float g_s[Bb*Cc*Tt];       // 0.5 * (fwd + bwd EWMA of diff)  [b][c][t]
__device__ float g_wc[Cc*Dd];         // Wcomb c-major: g_wc[c*Dd + e]
__device__ float g_bcomb[Dd];         // W_lin @ b_ve + b_lin

#define FMA_F32X2(d, a, b, c) \
    asm("fma.rn.f32x2 %0, %1, %2, %3;" : "=l"(d) : "l"(a), "l"(b), "l"(c))
#define PACK_DUP(d, f) \
    asm("mov.b64 %0, {%1, %1};" : "=l"(d) : "f"(f))

static __device__ __forceinline__ float2 unpack_f32x2(unsigned long long v) {
    float2 r;
    asm("mov.b64 {%0, %1}, %2;" : "=f"(r.x), "=f"(r.y) : "l"(v));
    return r;
}

// ---------------------------------------------------------------------------
// P: smem-tiled mini-GEMM for Wcomb = W_lin @ W_ve (c-major out) + bias.
// (measured ~4us, unchanged)
// ---------------------------------------------------------------------------
__global__ void __launch_bounds__(256) prep_kernel(
    const float* __restrict__ W_ve, const float* __restrict__ b_ve,
    const float* __restrict__ W_lin, const float* __restrict__ b_lin)
{
    __shared__ float wlin_sm[128 * 17];
    __shared__ float wve_sm[128 * 36];

    int tid = threadIdx.x;
    int e0 = blockIdx.x * PE;
    int tx = tid & 15;
    int ty = tid >> 4;

    float2 acc = make_float2(0.f, 0.f);

    for (int ch = 0; ch < 4; ch++) {
        int dBase = ch * 128;
        __syncthreads();

        #pragma unroll
        for (int k = 0; k < 2; k++) {
            int idx = tid + k * 256;
            int e   = idx >> 5;
            int d4  = (idx & 31) * 4;
            float4 w = *(const float4*)(W_lin + (size_t)(e0 + e) * Dd + dBase + d4);
            wlin_sm[(d4 + 0) * 17 + e] = w.x;
            wlin_sm[(d4 + 1) * 17 + e] = w.y;
            wlin_sm[(d4 + 2) * 17 + e] = w.z;
            wlin_sm[(d4 + 3) * 17 + e] = w.w;
        }
        #pragma unroll
        for (int k = 0; k < 4; k++) {
            int idx = tid + k * 256;
            int d   = idx >> 3;
            int c4  = (idx & 7) * 4;
            float4 v = *(const float4*)(W_ve + (size_t)(dBase + d) * Cc + c4);
            *(float4*)&wve_sm[d * 36 + c4] = v;
        }
        __syncthreads();

        #pragma unroll 8
        for (int dl = 0; dl < 128; dl++) {
            float  wl  = wlin_sm[dl * 17 + ty];
            float2 wv2 = *(const float2*)&wve_sm[dl * 36 + tx * 2];
            acc.x = fmaf(wl, wv2.x, acc.x);
            acc.y = fmaf(wl, wv2.y, acc.y);
        }
    }

    int e = e0 + ty;
    g_wc[(2 * tx)     * Dd + e] = acc.x;
    g_wc[(2 * tx + 1) * Dd + e] = acc.y;

    const unsigned FULL = 0xffffffffu;
    int wid  = tid >> 5;
    int lane = tid & 31;
    #pragma unroll
    for (int r = 0; r < 2; r++) {
        int eb = e0 + 2 * wid + r;
        float a = 0.f;
        #pragma unroll
        for (int i = 0; i < 16; i++) {
            int d = lane + 32 * i;
            a = fmaf(W_lin[(size_t)eb * Dd + d], b_ve[d], a);
        }
        a += __shfl_down_sync(FULL, a, 16);
        a += __shfl_down_sync(FULL, a, 8);
        a += __shfl_down_sync(FULL, a, 4);
        a += __shfl_down_sync(FULL, a, 2);
        a += __shfl_down_sync(FULL, a, 1);
        if (lane == 0) g_bcomb[eb] = a + b_lin[eb];
    }
}

// ---------------------------------------------------------------------------
// S: fused bidirectional EWMA, SEG=512 with 256-element warm-up.
// Warm fraction drops to 1/3 (was 1/2). One warp per (row, segment);
// forward keeps both real chunks in Ff[2][8] until the backward pass
// combines (shfl_xor 31, element-reversed) and stores 0.5*(f+g) once.
// ---------------------------------------------------------------------------
__global__ void __launch_bounds__(256) scan_kernel(const float* __restrict__ x)
{
    const unsigned FULL = 0xffffffffu;
    int g    = blockIdx.x * 8 + (threadIdx.x >> 5);
    int lane = threadIdx.x & 31;
    int bc   = g >> 2;            // row (b*Cc + c)
    int seg  = g & 3;

    const float* row = x + (size_t)bc * Tt;
    float*      srow = g_s + (size_t)bc * Tt;
    int lo = seg * SEG;
    int hi = lo + SEG;

    const float q   = 0.43046721f;              // 0.9^8
    const float q2  = q * q;
    const float q4  = q2 * q2;
    const float q8  = q4 * q4;
    const float q16 = q8 * q8;
    float blE;
    {
        float p = 1.f, base = q;
        int n = lane;
        while (n) { if (n & 1) p *= base; base *= base; n >>= 1; }
        blE = p;
    }
    const float B256 = 1.9e-12f;    // decay across one 256-chunk (0.9^256)

    float Ff[2][8];                 // forward results for the two real chunks

    // ---------------- forward pass ----------------
    {
        float warpCarry = 0.f;
        int t0 = (seg == 0) ? lo : (lo - 256);
        for (; t0 < hi; t0 += 256) {
            int tb = t0 + lane * 8;
            float4 a  = *(const float4*)(row + tb);
            float4 bq = *(const float4*)(row + tb + 4);
            float e[8] = {a.x, a.y, a.z, a.w, bq.x, bq.y, bq.z, bq.w};
            float prev = __shfl_up_sync(FULL, bq.w, 1);
            if (lane == 0) prev = (tb > 0) ? row[tb - 1] : 0.f;

            float L[8];
            L[0] = (tb == 0) ? 0.f : ALPHA * (e[0] - prev);
            #pragma unroll
            for (int j = 1; j < 8; j++)
                L[j] = fmaf(BETA, L[j - 1], ALPHA * (e[j] - e[j - 1]));

            float v = L[7], vo;
            vo = __shfl_up_sync(FULL, v, 1);  if (lane >= 1)  v = fmaf(q,   vo, v);
            vo = __shfl_up_sync(FULL, v, 2);  if (lane >= 2)  v = fmaf(q2,  vo, v);
            vo = __shfl_up_sync(FULL, v, 4);  if (lane >= 4)  v = fmaf(q4,  vo, v);
            vo = __shfl_up_sync(FULL, v, 8);  if (lane >= 8)  v = fmaf(q8,  vo, v);
            vo = __shfl_up_sync(FULL, v, 16); if (lane >= 16) v = fmaf(q16, vo, v);
            float vprev = __shfl_up_sync(FULL, v, 1);
            if (lane == 0) vprev = 0.f;
            float C = fmaf(blE, warpCarry, vprev);

            if (t0 >= lo) {
                int idx = (t0 - lo) >> 8;     // 0 or 1
                float coef = BETA;
                #pragma unroll
                for (int j = 0; j < 8; j++) { Ff[idx][j] = fmaf(coef, C, L[j]); coef *= BETA; }
            }
            float v31 = __shfl_sync(FULL, v, 31);
            warpCarry = fmaf(B256, warpCarry, v31);
        }
    }

    // ---------------- backward pass + combine ----------------
    {
        bool last = (hi == Tt);
        float warpCarry = last ? (row[Tt - 1] - row[Tt - 2]) : 0.f;
        int tt = last ? (Tt - 1) : (hi + 255);
        for (; tt >= lo; tt -= 256) {
            int tb = tt - lane * 8;
            float4 a  = *(const float4*)(row + tb - 7);
            float4 bq = *(const float4*)(row + tb - 3);
            float e[8] = {bq.w, bq.z, bq.y, bq.x, a.w, a.z, a.y, a.x};
            float prev = __shfl_down_sync(FULL, bq.w, 1);
            if (lane == 31) prev = (tb - 8 >= 0) ? row[tb - 8] : 0.f;

            float L[8];
            L[0] = ALPHA * (e[0] - e[1]);
            #pragma unroll
            for (int j = 1; j < 7; j++)
                L[j] = fmaf(BETA, L[j - 1], ALPHA * (e[j] - e[j + 1]));
            {
                float d7 = (tb - 7 == 0) ? 0.f : (e[7] - prev);
                L[7] = fmaf(BETA, L[6], ALPHA * d7);
            }

            float v = L[7], vo;
            vo = __shfl_up_sync(FULL, v, 1);  if (lane >= 1)  v = fmaf(q,   vo, v);
            vo = __shfl_up_sync(FULL, v, 2);  if (lane >= 2)  v = fmaf(q2,  vo, v);
            vo = __shfl_up_sync(FULL, v, 4);  if (lane >= 4)  v = fmaf(q4,  vo, v);
            vo = __shfl_up_sync(FULL, v, 8);  if (lane >= 8)  v = fmaf(q8,  vo, v);
            vo = __shfl_up_sync(FULL, v, 16); if (lane >= 16) v = fmaf(q16, vo, v);
            float vprev = __shfl_up_sync(FULL, v, 1);
            if (lane == 0) vprev = 0.f;
            float C = fmaf(blE, warpCarry, vprev);

            if (tt < hi) {
                int idx = (tt - lo) >> 8;     // 1 then 0
                float Fb[8];
                float coef = BETA;
                #pragma unroll
                for (int j = 0; j < 8; j++) { Fb[j] = fmaf(coef, C, L[j]); coef *= BETA; }
                float recv[8];
                #pragma unroll
                for (int j = 0; j < 8; j++)
                    recv[j] = __shfl_xor_sync(FULL, Fb[j], 31);
                int tbf = lo + idx * 256 + lane * 8;
                float4 o0 = make_float4(0.5f * (Ff[idx][0] + recv[7]),
                                        0.5f * (Ff[idx][1] + recv[6]),
                                        0.5f * (Ff[idx][2] + recv[5]),
                                        0.5f * (Ff[idx][3] + recv[4]));
                float4 o1 = make_float4(0.5f * (Ff[idx][4] + recv[3]),
                                        0.5f * (Ff[idx][5] + recv[2]),
                                        0.5f * (Ff[idx][6] + recv[1]),
                                        0.5f * (Ff[idx][7] + recv[0]));
                *(float4*)(srow + tbf)     = o0;
                *(float4*)(srow + tbf + 4) = o1;
            }
            float v31 = __shfl_sync(FULL, v, 31);
            warpCarry = fmaf(B256, warpCarry, v31);
        }
    }
}

// ---------------------------------------------------------------------------
// G: register-blocked FFMA2 GEMM, 2 e-chunks per block (tile 128t x 256e).
// s staged ONCE and reused for both W chunks; mainloop/epilogue per chunk
// identical to the measured 43.8us R10 kernel. 2 CTA/SM.
// ---------------------------------------------------------------------------
__global__ void __launch_bounds__(256, 2) gemm_kernel(float* __restrict__ out)
{
    __shared__ float ssm[Cc][128];     // [c][t_local] natural, 16 KB
    __shared__ float wsm[Cc][128];     // [c][e_local] natural, 16 KB

    int tid = threadIdx.x;
    int tx = tid & 15;
    int ty = tid >> 4;
    int b = blockIdx.z;
    int tBase = blockIdx.x * 128;

    // Stage s once: 32c x 128t, coalesced float4 over t.
    #pragma unroll
    for (int k = 0; k < 4; k++) {
        int idx = tid + k * 256;          // 0..1023
        int c   = idx >> 5;               // 0..31
        int tl  = (idx & 31) * 4;         // 0..124
        size_t off = ((size_t)(b * Cc + c)) * Tt + tBase + tl;
        *(float4*)&ssm[c][tl] = *(const float4*)(g_s + off);
    }

    #pragma unroll
    for (int ch = 0; ch < 2; ch++) {
        int eBase = blockIdx.y * 256 + ch * 128;
        if (ch > 0) __syncthreads();   // previous chunk readers done with wsm
        #pragma unroll
        for (int k = 0; k < 4; k++) {
            int idx = tid + k * 256;
            int c   = idx >> 5;
            int e4  = (idx & 31) * 4;
            *(float4*)&wsm[c][e4] = *(const float4*)(g_wc + (size_t)c * Dd + eBase + e4);
        }
        __syncthreads();

        unsigned long long acc[8][4];
        #pragma unroll
        for (int i = 0; i < 8; i++)
            #pragma unroll
            for (int p = 0; p < 4; p++) acc[i][p] = 0ull;

        #pragma unroll
        for (int c = 0; c < Cc; c++) {
            float4 s0 = *(const float4*)&ssm[c][ty * 8];
            float4 s1 = *(const float4*)&ssm[c][ty * 8 + 4];
            float sf[8] = {s0.x, s0.y, s0.z, s0.w, s1.x, s1.y, s1.z, s1.w};
            unsigned long long sv[8];
            #pragma unroll
            for (int i = 0; i < 8; i++) PACK_DUP(sv[i], sf[i]);

            ulonglong2 w0 = *(const ulonglong2*)&wsm[c][4 * tx];
            ulonglong2 w1 = *(const ulonglong2*)&wsm[c][4 * tx + 64];
            #pragma unroll
            for (int i = 0; i < 8; i++) {
                FMA_F32X2(acc[i][0], sv[i], w0.x, acc[i][0]);
                FMA_F32X2(acc[i][1], sv[i], w0.y, acc[i][1]);
                FMA_F32X2(acc[i][2], sv[i], w1.x, acc[i][2]);
                FMA_F32X2(acc[i][3], sv[i], w1.y, acc[i][3]);
            }
        }

        float4 bias0 = *(const float4*)(g_bcomb + eBase + 4 * tx);
        float4 bias1 = *(const float4*)(g_bcomb + eBase + 4 * tx + 64);

        #pragma unroll
        for (int i = 0; i < 8; i++) {
            int t = tBase + ty * 8 + i;
            float* base = out + ((size_t)(b * Tt + t)) * Dd + eBase;
            float2 r0 = unpack_f32x2(acc[i][0]);
            float2 r1 = unpack_f32x2(acc[i][1]);
            float2 r2 = unpack_f32x2(acc[i][2]);
            float2 r3 = unpack_f32x2(acc[i][3]);
            float4 o0 = make_float4(r0.x + bias0.x, r0.y + bias0.y,
                                    r1.x + bias0.z, r1.y + bias0.w);
            float4 o1 = make_float4(r2.x + bias1.x, r2.y + bias1.y,
                                    r3.x + bias1.z, r3.y + bias1.w);
            *(float4*)(base + 4 * tx)      = o0;
            *(float4*)(base + 4 * tx + 64) = o1;
        }
    }
}

// ---------------------------------------------------------------------------
extern "C" void kernel_launch(void* const* d_in, const int* in_sizes, int n_in,
                              void* d_out, int out_size)
{
    const float* x     = (const float*)d_in[0];   // [B, C, T]
    const float* W_ve  = (const float*)d_in[1];   // [D, C]
    const float* b_ve  = (const float*)d_in[2];   // [D]
    const float* W_lin = (const float*)d_in[3];   // [D, D]
    const float* b_lin = (const float*)d_in[4];   // [D]
    float* out = (float*)d_out;                   // [B, T, D]

    scan_kernel<<<NSCAN_BLK, 256>>>(x);
    prep_kernel<<<Dd / PE, 256>>>(W_ve, b_ve, W_lin, b_lin);

    dim3 grid(Tt / 128, Dd / 256, Bb);
    gemm_kernel<<<grid, 256>>>(out);
}